// round 14
// baseline (speedup 1.0000x reference)
#include <cuda_runtime.h>

#define NN 50000
#define EE 800000
#define FF 100
#define HH 64
#define CC 40
#define W1CAT 192    // [A=x@W1[1] | B=x@W1[2] | C0=x@(W1[0]-W1[2])]
#define W2CAT 120    // logical [A2 | B2 | C2]
#define HWPAD 128    // padded row stride for g_HW (alignment)
#define SCAN_BLOCKS ((NN + 255) / 256)   // 196

// ---------------- scratch (device globals; no allocations allowed) ----------
__device__ int   g_is64;
__device__ int   g_deg[NN];
__device__ int   g_rowptr[NN + 1];
__device__ int   g_cursor[NN];
__device__ int   g_bsum[SCAN_BLOCKS];
__device__ int2  g_cw[EE];           // packed (col, weight-bits)
__device__ float g_dinv[NN];
__device__ float g_Wcat1[FF * W1CAT];
__device__ float g_Wcat2[HH * W2CAT];
__device__ float g_XW[NN * W1CAT];
__device__ float g_U[NN * HH];
__device__ float g_h[NN * HH];
__device__ float g_HW[NN * HWPAD];   // padded: cols 0..119 valid
__device__ float g_U2[NN * 64];      // padded: cols 0..39 valid

// ---------------- dtype detection (parallel) ---------------------------------
__global__ void k_detect_dtype(const long long* __restrict__ ei) {
    __shared__ int s_ok;
    int tid = threadIdx.x;            // 1024 threads
    if (tid == 0) s_ok = 1;
    __syncthreads();
    long long v = ei[tid * 781];      // max index 1023*781 = 798,963 < EE
    if (v < 0 || v >= NN) s_ok = 0;   // benign race: only 0 written
    __syncthreads();
    if (tid == 0) g_is64 = s_ok;
}

// ---------------- init: zero degrees + weight concat (merged) ----------------
__global__ void k_init(const float* __restrict__ W1, const float* __restrict__ W2) {
    int i = blockIdx.x * blockDim.x + threadIdx.x;
    if (i < NN) g_deg[i] = 0;
    if (i < FF * W1CAT) {
        int f = i / W1CAT, j = i % W1CAT;
        float v;
        if (j < 64)       v = W1[6400 + f * 64 + j];
        else if (j < 128) v = W1[12800 + f * 64 + (j - 64)];
        else              v = W1[f * 64 + (j - 128)] - W1[12800 + f * 64 + (j - 128)];
        g_Wcat1[i] = v;
    }
    if (i < HH * W2CAT) {
        int f = i / W2CAT, j = i % W2CAT;
        float v;
        if (j < 40)      v = W2[2560 + f * 40 + j];
        else if (j < 80) v = W2[5120 + f * 40 + (j - 40)];
        else             v = W2[f * 40 + (j - 80)] - W2[5120 + f * 40 + (j - 80)];
        g_Wcat2[i] = v;
    }
}

// ---------------- graph setup ------------------------------------------------
__global__ void k_count_deg(const long long* __restrict__ ei64,
                            const int* __restrict__ ei32) {
    int e = blockIdx.x * blockDim.x + threadIdx.x;
    if (e < EE) {
        long long r = g_is64 ? ei64[e] : (long long)ei32[e];
        if (r >= 0 && r < NN) atomicAdd(&g_deg[(int)r], 1);
    }
}

// -------- 3-phase multi-block exclusive scan ---------------------------------
__global__ void k_scan1() {
    __shared__ int warpsums[8];
    int tid = threadIdx.x;
    int i = blockIdx.x * 256 + tid;
    int d = (i < NN) ? g_deg[i] : 0;

    int lane = tid & 31, wid = tid >> 5;
    int v = d;
    #pragma unroll
    for (int o = 1; o < 32; o <<= 1) {
        int t = __shfl_up_sync(0xffffffffu, v, o);
        if (lane >= o) v += t;
    }
    if (lane == 31) warpsums[wid] = v;
    __syncthreads();
    if (tid == 0) {
        int run = 0;
        #pragma unroll
        for (int k = 0; k < 8; k++) { int t = warpsums[k]; warpsums[k] = run; run += t; }
    }
    __syncthreads();
    int excl = v - d + warpsums[wid];
    if (i < NN) g_rowptr[i] = excl;
    if (tid == 255) g_bsum[blockIdx.x] = excl + d;
}

__global__ void k_scan2() {
    __shared__ int warpsums[8];
    int tid = threadIdx.x;   // 256 threads
    int v0 = (tid < SCAN_BLOCKS) ? g_bsum[tid] : 0;

    int lane = tid & 31, wid = tid >> 5;
    int v = v0;
    #pragma unroll
    for (int o = 1; o < 32; o <<= 1) {
        int t = __shfl_up_sync(0xffffffffu, v, o);
        if (lane >= o) v += t;
    }
    if (lane == 31) warpsums[wid] = v;
    __syncthreads();
    if (tid == 0) {
        int run = 0;
        #pragma unroll
        for (int k = 0; k < 8; k++) { int t = warpsums[k]; warpsums[k] = run; run += t; }
    }
    __syncthreads();
    if (tid < SCAN_BLOCKS) g_bsum[tid] = v - v0 + warpsums[wid];
}

__global__ void k_scan3() {
    int i = blockIdx.x * 256 + threadIdx.x;
    if (i < NN) {
        int r = g_rowptr[i] + g_bsum[blockIdx.x];
        g_rowptr[i] = r;
        g_cursor[i] = r;
        int d = g_deg[i];
        g_dinv[i] = (d > 0) ? rsqrtf((float)d) : 0.0f;
        if (i == NN - 1) g_rowptr[NN] = r + d;
    }
}

__global__ void k_fill_csr(const long long* __restrict__ ei64,
                           const int* __restrict__ ei32) {
    int e = blockIdx.x * blockDim.x + threadIdx.x;
    if (e < EE) {
        long long rl, cl;
        if (g_is64) { rl = ei64[e]; cl = ei64[EE + e]; }
        else        { rl = (long long)ei32[e]; cl = (long long)ei32[EE + e]; }
        if (rl < 0 || rl >= NN || cl < 0 || cl >= NN) return;
        int r = (int)rl, c = (int)cl;
        int pos = atomicAdd(&g_cursor[r], 1);
        if (pos >= 0 && pos < EE) {
            float wt = -(g_dinv[r] * g_dinv[c]);
            g_cw[pos] = make_int2(c, __float_as_int(wt));
        }
    }
}

// ---------------- SIMT fp32 GEMM: 64x64 block tile, 4x4 per thread ----------
template <int Kd, int Nc, int Ldc>
__device__ __forceinline__ void gemm_core(
    const float* __restrict__ A, const float* __restrict__ B, float* __restrict__ C)
{
    __shared__ __align__(16) float As[16][68];
    __shared__ __align__(16) float Bs[16][68];
    const int M = NN;
    int tid = threadIdx.x;
    int tx = tid % 16, ty = tid / 16;
    int m0 = blockIdx.x * 64, n0 = blockIdx.y * 64;

    float acc[4][4];
    #pragma unroll
    for (int i = 0; i < 4; i++)
        #pragma unroll
        for (int j = 0; j < 4; j++) acc[i][j] = 0.0f;

    for (int k0 = 0; k0 < Kd; k0 += 16) {
        #pragma unroll
        for (int i = tid; i < 64 * 16; i += 256) {
            int k = i % 16, m = i / 16;
            int gm = m0 + m, gk = k0 + k;
            As[k][m] = (gm < M && gk < Kd) ? A[gm * Kd + gk] : 0.0f;
        }
        #pragma unroll
        for (int i = tid; i < 16 * 64; i += 256) {
            int n = i % 64, k = i / 64;
            int gk = k0 + k, gn = n0 + n;
            Bs[k][n] = (gk < Kd && gn < Nc) ? B[gk * Nc + gn] : 0.0f;
        }
        __syncthreads();
        #pragma unroll
        for (int k = 0; k < 16; k++) {
            float4 av = *(const float4*)&As[k][ty * 4];
            float4 bv = *(const float4*)&Bs[k][tx * 4];
            float a[4] = {av.x, av.y, av.z, av.w};
            float b[4] = {bv.x, bv.y, bv.z, bv.w};
            #pragma unroll
            for (int i = 0; i < 4; i++)
                #pragma unroll
                for (int j = 0; j < 4; j++) acc[i][j] += a[i] * b[j];
        }
        __syncthreads();
    }
    #pragma unroll
    for (int i = 0; i < 4; i++) {
        int gm = m0 + ty * 4 + i;
        if (gm >= M) continue;
        #pragma unroll
        for (int j = 0; j < 4; j++) {
            int gn = n0 + tx * 4 + j;
            if (gn < Nc) C[gm * Ldc + gn] = acc[i][j];
        }
    }
}

__global__ __launch_bounds__(256) void k_gemm1(const float* __restrict__ x) {
    gemm_core<FF, W1CAT, W1CAT>(x, g_Wcat1, g_XW);
}

__global__ __launch_bounds__(256) void k_gemm2() {
    gemm_core<HH, W2CAT, HWPAD>(g_h, g_Wcat2, g_HW);   // padded output stride
}

// ---------------- SpMV kernels (2 edges/warp, float4 gathers) ----------------
// U = A + 2*L*B   (A at XW cols 0..63, B at cols 64..127)
__global__ void k_spmv_U() {
    int w = (blockIdx.x * blockDim.x + threadIdx.x) >> 5;
    int lane = threadIdx.x & 31;
    if (w >= NN) return;
    int s = g_rowptr[w], e = g_rowptr[w + 1];
    int half = lane >> 4, hl = lane & 15;       // 16 lanes x float4 = 64 floats

    float4 acc = make_float4(0.f, 0.f, 0.f, 0.f);
    for (int t = s; t < e; t += 2) {
        int idx = t + half;
        if (idx < e) {
            int2 cw = g_cw[idx];
            float wt = __int_as_float(cw.y);
            float4 v = *(const float4*)&g_XW[cw.x * W1CAT + 64 + hl * 4];
            acc.x += wt * v.x; acc.y += wt * v.y; acc.z += wt * v.z; acc.w += wt * v.w;
        }
    }
    acc.x += __shfl_xor_sync(0xffffffffu, acc.x, 16);
    acc.y += __shfl_xor_sync(0xffffffffu, acc.y, 16);
    acc.z += __shfl_xor_sync(0xffffffffu, acc.z, 16);
    acc.w += __shfl_xor_sync(0xffffffffu, acc.w, 16);
    if (half == 0) {
        float4 a = *(const float4*)&g_XW[w * W1CAT + hl * 4];
        float4 o = make_float4(a.x + 2.f * acc.x, a.y + 2.f * acc.y,
                               a.z + 2.f * acc.z, a.w + 2.f * acc.w);
        *(float4*)&g_U[w * HH + hl * 4] = o;
    }
}

// h = relu(C0 + L*U + b1)   (C0 at XW cols 128..191)
__global__ void k_spmv_h(const float* __restrict__ b1) {
    int w = (blockIdx.x * blockDim.x + threadIdx.x) >> 5;
    int lane = threadIdx.x & 31;
    if (w >= NN) return;
    int s = g_rowptr[w], e = g_rowptr[w + 1];
    int half = lane >> 4, hl = lane & 15;

    float4 acc = make_float4(0.f, 0.f, 0.f, 0.f);
    for (int t = s; t < e; t += 2) {
        int idx = t + half;
        if (idx < e) {
            int2 cw = g_cw[idx];
            float wt = __int_as_float(cw.y);
            float4 v = *(const float4*)&g_U[cw.x * HH + hl * 4];
            acc.x += wt * v.x; acc.y += wt * v.y; acc.z += wt * v.z; acc.w += wt * v.w;
        }
    }
    acc.x += __shfl_xor_sync(0xffffffffu, acc.x, 16);
    acc.y += __shfl_xor_sync(0xffffffffu, acc.y, 16);
    acc.z += __shfl_xor_sync(0xffffffffu, acc.z, 16);
    acc.w += __shfl_xor_sync(0xffffffffu, acc.w, 16);
    if (half == 0) {
        float4 c0 = *(const float4*)&g_XW[w * W1CAT + 128 + hl * 4];
        float4 bb = *(const float4*)&b1[hl * 4];
        *(float4*)&g_h[w * HH + hl * 4] = make_float4(
            fmaxf(c0.x + acc.x + bb.x, 0.f), fmaxf(c0.y + acc.y + bb.y, 0.f),
            fmaxf(c0.z + acc.z + bb.z, 0.f), fmaxf(c0.w + acc.w + bb.w, 0.f));
    }
}

// U2 = A2 + 2*L*B2   (A2 at HW cols 0..39, B2 at cols 40..79; padded stride)
__global__ void k_spmv_U2() {
    int w = (blockIdx.x * blockDim.x + threadIdx.x) >> 5;
    int lane = threadIdx.x & 31;
    if (w >= NN) return;
    int s = g_rowptr[w], e = g_rowptr[w + 1];
    int half = lane >> 4, hl = lane & 15;       // hl<10 active (40 floats)

    float4 acc = make_float4(0.f, 0.f, 0.f, 0.f);
    for (int t = s; t < e; t += 2) {
        int idx = t + half;
        if (idx < e && hl < 10) {
            int2 cw = g_cw[idx];
            float wt = __int_as_float(cw.y);
            float4 v = *(const float4*)&g_HW[cw.x * HWPAD + 40 + hl * 4];
            acc.x += wt * v.x; acc.y += wt * v.y; acc.z += wt * v.z; acc.w += wt * v.w;
        }
    }
    acc.x += __shfl_xor_sync(0xffffffffu, acc.x, 16);
    acc.y += __shfl_xor_sync(0xffffffffu, acc.y, 16);
    acc.z += __shfl_xor_sync(0xffffffffu, acc.z, 16);
    acc.w += __shfl_xor_sync(0xffffffffu, acc.w, 16);
    if (half == 0 && hl < 10) {
        float4 a = *(const float4*)&g_HW[w * HWPAD + hl * 4];
        *(float4*)&g_U2[w * 64 + hl * 4] = make_float4(
            a.x + 2.f * acc.x, a.y + 2.f * acc.y, a.z + 2.f * acc.z, a.w + 2.f * acc.w);
    }
}

// logits = C2 + L*U2 + b2 ; out = log_softmax (C2 at HW cols 80..119)
__global__ void k_final(const float* __restrict__ b2, float* __restrict__ out) {
    int w = (blockIdx.x * blockDim.x + threadIdx.x) >> 5;
    int lane = threadIdx.x & 31;
    if (w >= NN) return;
    int s = g_rowptr[w], e = g_rowptr[w + 1];
    int half = lane >> 4, hl = lane & 15;

    float4 acc = make_float4(0.f, 0.f, 0.f, 0.f);
    for (int t = s; t < e; t += 2) {
        int idx = t + half;
        if (idx < e && hl < 10) {
            int2 cw = g_cw[idx];
            float wt = __int_as_float(cw.y);
            float4 v = *(const float4*)&g_U2[cw.x * 64 + hl * 4];
            acc.x += wt * v.x; acc.y += wt * v.y; acc.z += wt * v.z; acc.w += wt * v.w;
        }
    }
    acc.x += __shfl_xor_sync(0xffffffffu, acc.x, 16);
    acc.y += __shfl_xor_sync(0xffffffffu, acc.y, 16);
    acc.z += __shfl_xor_sync(0xffffffffu, acc.z, 16);
    acc.w += __shfl_xor_sync(0xffffffffu, acc.w, 16);

    // logits held as float4 in lanes hl<10 (both halves duplicate)
    float4 z = make_float4(0.f, 0.f, 0.f, 0.f);
    if (hl < 10) {
        float4 c2 = *(const float4*)&g_HW[w * HWPAD + 80 + hl * 4];
        float4 bb = *(const float4*)&b2[hl * 4];
        z = make_float4(c2.x + acc.x + bb.x, c2.y + acc.y + bb.y,
                        c2.z + acc.z + bb.z, c2.w + acc.w + bb.w);
    }
    // warp max over the 40 logits
    const float NEG_INF = __int_as_float(0xff800000);
    float m = (hl < 10) ? fmaxf(fmaxf(z.x, z.y), fmaxf(z.z, z.w)) : NEG_INF;
    #pragma unroll
    for (int o = 16; o > 0; o >>= 1) m = fmaxf(m, __shfl_xor_sync(0xffffffffu, m, o));
    // warp sum of exp (count each feature once: half 0 only)
    float ssum = 0.f;
    if (half == 0 && hl < 10)
        ssum = expf(z.x - m) + expf(z.y - m) + expf(z.z - m) + expf(z.w - m);
    #pragma unroll
    for (int o = 16; o > 0; o >>= 1) ssum += __shfl_xor_sync(0xffffffffu, ssum, o);
    float l = logf(ssum);
    if (half == 0 && hl < 10) {
        *(float4*)&out[w * CC + hl * 4] = make_float4(z.x - m - l, z.y - m - l,
                                                      z.z - m - l, z.w - m - l);
    }
}

// ---------------- launch -----------------------------------------------------
extern "C" void kernel_launch(void* const* d_in, const int* in_sizes, int n_in,
                              void* d_out, int out_size) {
    // Resolve inputs BY ELEMENT COUNT (all six distinct)
    const float* x  = nullptr;
    const void*  ei = nullptr;
    const float* W1 = nullptr;
    const float* b1 = nullptr;
    const float* W2 = nullptr;
    const float* b2 = nullptr;
    for (int i = 0; i < n_in; i++) {
        switch (in_sizes[i]) {
            case NN * FF:     x  = (const float*)d_in[i]; break;
            case 2 * EE:      ei = d_in[i];               break;
            case 3 * FF * HH: W1 = (const float*)d_in[i]; break;
            case HH:          b1 = (const float*)d_in[i]; break;
            case 3 * HH * CC: W2 = (const float*)d_in[i]; break;
            case CC:          b2 = (const float*)d_in[i]; break;
            default: break;
        }
    }
    const long long* ei64 = (const long long*)ei;
    const int*       ei32 = (const int*)ei;
    float* out = (float*)d_out;

    const int TB = 256;
    int nodeBlocks = (NN + TB - 1) / TB;
    int edgeBlocks = (EE + TB - 1) / TB;
    int warpRowBlocks = (NN * 32 + TB - 1) / TB;

    k_detect_dtype<<<1, 1024>>>(ei64);            // #1
    k_init<<<nodeBlocks, TB>>>(W1, W2);           // #2
    k_count_deg<<<edgeBlocks, TB>>>(ei64, ei32);  // #3
    {   // #4 — ncu profiles this slot; depends only on k_init
        dim3 grid((NN + 63) / 64, (W1CAT + 63) / 64);
        k_gemm1<<<grid, 256>>>(x);
    }
    k_scan1<<<SCAN_BLOCKS, 256>>>();              // #5
    k_scan2<<<1, 256>>>();                        // #6
    k_scan3<<<SCAN_BLOCKS, 256>>>();              // #7
    k_fill_csr<<<edgeBlocks, TB>>>(ei64, ei32);   // #8

    k_spmv_U<<<warpRowBlocks, TB>>>();
    k_spmv_h<<<warpRowBlocks, TB>>>(b1);

    {
        dim3 grid((NN + 63) / 64, (W2CAT + 63) / 64);
        k_gemm2<<<grid, 256>>>();
    }
    k_spmv_U2<<<warpRowBlocks, TB>>>();
    k_final<<<warpRowBlocks, TB>>>(b2, out);
}

// round 15
// speedup vs baseline: 1.1376x; 1.1376x over previous
#include <cuda_runtime.h>

#define NN 50000
#define EE 800000
#define FF 100
#define HH 64
#define CC 40
#define W1CAT 192    // [A=x@W1[1] | B=x@W1[2] | C0=x@(W1[0]-W1[2])]
#define W2CAT 120    // logical [A2 | B2 | C2]
#define HWPAD 128    // padded row stride for g_HW
#define SCAN_BLOCKS ((NN + 255) / 256)   // 196

typedef unsigned long long ull;

// ---------------- scratch (device globals; no allocations allowed) ----------
__device__ int   g_is64;
__device__ int   g_deg[NN];
__device__ int   g_rowptr[NN + 1];
__device__ int   g_cursor[NN];
__device__ int   g_bsum[SCAN_BLOCKS];
__device__ int2  g_cw[EE];           // packed (col, weight-bits)
__device__ float g_dinv[NN];
__device__ float g_Wcat1[FF * W1CAT];
__device__ float g_Wcat2[HH * W2CAT];
__device__ float g_XW[NN * W1CAT];
__device__ float g_U[NN * HH];
__device__ float g_h[NN * HH];
__device__ float g_HW[NN * HWPAD];   // cols 0..119 valid
__device__ float g_U2[NN * 64];      // cols 0..39 valid

// ---------------- f32x2 helpers ----------------------------------------------
#define FMA2(d, a, b, c) \
    asm("fma.rn.f32x2 %0, %1, %2, %3;" : "=l"(d) : "l"(a), "l"(b), "l"(c))

__device__ __forceinline__ ull pack2(float lo, float hi) {
    ull r; asm("mov.b64 %0, {%1, %2};" : "=l"(r) : "f"(lo), "f"(hi)); return r;
}
__device__ __forceinline__ float2 unpack2(ull v) {
    float2 r; asm("mov.b64 {%0, %1}, %2;" : "=f"(r.x), "=f"(r.y) : "l"(v)); return r;
}

// ---------------- dtype detection (parallel) ---------------------------------
__global__ void k_detect_dtype(const long long* __restrict__ ei) {
    __shared__ int s_ok;
    int tid = threadIdx.x;            // 1024 threads
    if (tid == 0) s_ok = 1;
    __syncthreads();
    long long v = ei[tid * 781];      // max index 798,963 < EE
    if (v < 0 || v >= NN) s_ok = 0;
    __syncthreads();
    if (tid == 0) g_is64 = s_ok;
}

// ---------------- init: zero degrees + weight concat (merged) ----------------
__global__ void k_init(const float* __restrict__ W1, const float* __restrict__ W2) {
    int i = blockIdx.x * blockDim.x + threadIdx.x;
    if (i < NN) g_deg[i] = 0;
    if (i < FF * W1CAT) {
        int f = i / W1CAT, j = i % W1CAT;
        float v;
        if (j < 64)       v = W1[6400 + f * 64 + j];
        else if (j < 128) v = W1[12800 + f * 64 + (j - 64)];
        else              v = W1[f * 64 + (j - 128)] - W1[12800 + f * 64 + (j - 128)];
        g_Wcat1[i] = v;
    }
    if (i < HH * W2CAT) {
        int f = i / W2CAT, j = i % W2CAT;
        float v;
        if (j < 40)      v = W2[2560 + f * 40 + j];
        else if (j < 80) v = W2[5120 + f * 40 + (j - 40)];
        else             v = W2[f * 40 + (j - 80)] - W2[5120 + f * 40 + (j - 80)];
        g_Wcat2[i] = v;
    }
}

// ---------------- graph setup ------------------------------------------------
__global__ void k_count_deg(const long long* __restrict__ ei64,
                            const int* __restrict__ ei32) {
    int e = blockIdx.x * blockDim.x + threadIdx.x;
    if (e < EE) {
        long long r = g_is64 ? ei64[e] : (long long)ei32[e];
        if (r >= 0 && r < NN) atomicAdd(&g_deg[(int)r], 1);
    }
}

__global__ void k_scan1() {
    __shared__ int warpsums[8];
    int tid = threadIdx.x;
    int i = blockIdx.x * 256 + tid;
    int d = (i < NN) ? g_deg[i] : 0;

    int lane = tid & 31, wid = tid >> 5;
    int v = d;
    #pragma unroll
    for (int o = 1; o < 32; o <<= 1) {
        int t = __shfl_up_sync(0xffffffffu, v, o);
        if (lane >= o) v += t;
    }
    if (lane == 31) warpsums[wid] = v;
    __syncthreads();
    if (tid == 0) {
        int run = 0;
        #pragma unroll
        for (int k = 0; k < 8; k++) { int t = warpsums[k]; warpsums[k] = run; run += t; }
    }
    __syncthreads();
    int excl = v - d + warpsums[wid];
    if (i < NN) g_rowptr[i] = excl;
    if (tid == 255) g_bsum[blockIdx.x] = excl + d;
}

__global__ void k_scan2() {
    __shared__ int warpsums[8];
    int tid = threadIdx.x;   // 256 threads
    int v0 = (tid < SCAN_BLOCKS) ? g_bsum[tid] : 0;

    int lane = tid & 31, wid = tid >> 5;
    int v = v0;
    #pragma unroll
    for (int o = 1; o < 32; o <<= 1) {
        int t = __shfl_up_sync(0xffffffffu, v, o);
        if (lane >= o) v += t;
    }
    if (lane == 31) warpsums[wid] = v;
    __syncthreads();
    if (tid == 0) {
        int run = 0;
        #pragma unroll
        for (int k = 0; k < 8; k++) { int t = warpsums[k]; warpsums[k] = run; run += t; }
    }
    __syncthreads();
    if (tid < SCAN_BLOCKS) g_bsum[tid] = v - v0 + warpsums[wid];
}

__global__ void k_scan3() {
    int i = blockIdx.x * 256 + threadIdx.x;
    if (i < NN) {
        int r = g_rowptr[i] + g_bsum[blockIdx.x];
        g_rowptr[i] = r;
        g_cursor[i] = r;
        int d = g_deg[i];
        g_dinv[i] = (d > 0) ? rsqrtf((float)d) : 0.0f;
        if (i == NN - 1) g_rowptr[NN] = r + d;
    }
}

__global__ void k_fill_csr(const long long* __restrict__ ei64,
                           const int* __restrict__ ei32) {
    int e = blockIdx.x * blockDim.x + threadIdx.x;
    if (e < EE) {
        long long rl, cl;
        if (g_is64) { rl = ei64[e]; cl = ei64[EE + e]; }
        else        { rl = (long long)ei32[e]; cl = (long long)ei32[EE + e]; }
        if (rl < 0 || rl >= NN || cl < 0 || cl >= NN) return;
        int r = (int)rl, c = (int)cl;
        int pos = atomicAdd(&g_cursor[r], 1);
        if (pos >= 0 && pos < EE) {
            float wt = -(g_dinv[r] * g_dinv[c]);
            g_cw[pos] = make_int2(c, __float_as_int(wt));
        }
    }
}

// ---------------- f32x2 GEMM: BM=64, BN=full width, thread tile 4 x CPT ------
// A [M,Kd] row-major; B [Kd,NV] row-major; C [M,Ldc] (cols 0..NV-1 written).
// 256 threads as 16(tx) x 16(ty); thread covers rows ty*4+0..3, cols tx*CPT..+CPT-1.
// A is staged into shared PRE-DUPLICATED as (a,a) u64 pairs -> no per-k splat.
template <int Kd, int BN, int NV, int Ldc>
__device__ __forceinline__ void gemm_f2_core(
    const float* __restrict__ A, const float* __restrict__ B, float* __restrict__ C)
{
    constexpr int CPT = BN / 16;         // 12 or 8 cols per thread
    constexpr int PAIRS = CPT / 2;       // 6 or 4 f32x2 accumulators per row
    constexpr int BQ = BN / 4;           // float4s per Bs row
    constexpr int NB4 = (16 * BQ) / 256; // B float4 loads per thread per ktile

    __shared__ __align__(16) ull   As2[16][66];   // [k][m] = (A[m][k], A[m][k])
    __shared__ __align__(16) float Bs[16][BN];

    int tid = threadIdx.x;
    int tx = tid & 15, ty = tid >> 4;
    int m0 = blockIdx.x * 64;

    ull acc[4][PAIRS];
    #pragma unroll
    for (int i = 0; i < 4; i++)
        #pragma unroll
        for (int j = 0; j < PAIRS; j++) acc[i][j] = 0ull;   // (0.0f, 0.0f)

    for (int k0 = 0; k0 < Kd; k0 += 16) {
        // stage A: 1 float4 per thread, write duplicated pairs transposed
        {
            int m = tid >> 2, q = tid & 3;
            int gm = m0 + m, gk = k0 + q * 4;
            float4 v = make_float4(0.f, 0.f, 0.f, 0.f);
            if (gm < NN) {
                if (gk + 4 <= Kd) v = *(const float4*)&A[gm * Kd + gk];
                else {
                    float t0 = (gk + 0 < Kd) ? A[gm * Kd + gk + 0] : 0.f;
                    float t1 = (gk + 1 < Kd) ? A[gm * Kd + gk + 1] : 0.f;
                    float t2 = (gk + 2 < Kd) ? A[gm * Kd + gk + 2] : 0.f;
                    float t3 = (gk + 3 < Kd) ? A[gm * Kd + gk + 3] : 0.f;
                    v = make_float4(t0, t1, t2, t3);
                }
            }
            As2[q * 4 + 0][m] = pack2(v.x, v.x);
            As2[q * 4 + 1][m] = pack2(v.y, v.y);
            As2[q * 4 + 2][m] = pack2(v.z, v.z);
            As2[q * 4 + 3][m] = pack2(v.w, v.w);
        }
        // stage B
        #pragma unroll
        for (int c = 0; c < NB4; c++) {
            int idx = c * 256 + tid;
            int row = idx / BQ, c4 = idx % BQ;
            int gk = k0 + row, gn = c4 * 4;
            float4 v = make_float4(0.f, 0.f, 0.f, 0.f);
            if (gk < Kd) {
                if (gn + 4 <= NV) v = *(const float4*)&B[gk * NV + gn];
                else {
                    float t0 = (gn + 0 < NV) ? B[gk * NV + gn + 0] : 0.f;
                    float t1 = (gn + 1 < NV) ? B[gk * NV + gn + 1] : 0.f;
                    float t2 = (gn + 2 < NV) ? B[gk * NV + gn + 2] : 0.f;
                    float t3 = (gn + 3 < NV) ? B[gk * NV + gn + 3] : 0.f;
                    v = make_float4(t0, t1, t2, t3);
                }
            }
            *(float4*)&Bs[row][gn] = v;
        }
        __syncthreads();
        #pragma unroll
        for (int k = 0; k < 16; k++) {
            ulonglong2 aa0 = *(const ulonglong2*)&As2[k][ty * 4];
            ulonglong2 aa1 = *(const ulonglong2*)&As2[k][ty * 4 + 2];
            ull a2[4] = {aa0.x, aa0.y, aa1.x, aa1.y};
            ull b2[PAIRS];
            #pragma unroll
            for (int q = 0; q < PAIRS / 2; q++) {
                ulonglong2 bv = *(const ulonglong2*)&Bs[k][tx * CPT + q * 4];
                b2[q * 2] = bv.x; b2[q * 2 + 1] = bv.y;
            }
            #pragma unroll
            for (int i = 0; i < 4; i++)
                #pragma unroll
                for (int j = 0; j < PAIRS; j++)
                    FMA2(acc[i][j], a2[i], b2[j], acc[i][j]);
        }
        __syncthreads();
    }
    // epilogue: unpack pairs -> float4 stores (guard against NV)
    #pragma unroll
    for (int i = 0; i < 4; i++) {
        int gm = m0 + ty * 4 + i;
        if (gm >= NN) continue;
        #pragma unroll
        for (int q = 0; q < PAIRS / 2; q++) {
            int gn = tx * CPT + q * 4;
            if (gn + 4 <= NV) {
                float2 lo = unpack2(acc[i][q * 2]);
                float2 hi = unpack2(acc[i][q * 2 + 1]);
                *(float4*)&C[gm * Ldc + gn] = make_float4(lo.x, lo.y, hi.x, hi.y);
            }
        }
    }
}

__global__ __launch_bounds__(256) void k_gemm1(const float* __restrict__ x) {
    gemm_f2_core<FF, 192, 192, W1CAT>(x, g_Wcat1, g_XW);
}

__global__ __launch_bounds__(256) void k_gemm2() {
    gemm_f2_core<HH, 128, 120, HWPAD>(g_h, g_Wcat2, g_HW);
}

// ---------------- SpMV kernels (warp-per-row CSR gather, packed cw) ----------
// U = A + 2*L*B   (A at XW cols 0..63, B at cols 64..127)
__global__ void k_spmv_U() {
    int w = (blockIdx.x * blockDim.x + threadIdx.x) >> 5;
    int lane = threadIdx.x & 31;
    if (w >= NN) return;
    int s = g_rowptr[w], e = g_rowptr[w + 1];
    float a0 = 0.f, a1 = 0.f;
    for (int t = s; t < e; t++) {
        int2 cw = g_cw[t];
        float wt = __int_as_float(cw.y);
        const float* p = &g_XW[cw.x * W1CAT + 64];
        a0 += wt * p[lane];
        a1 += wt * p[32 + lane];
    }
    g_U[w * HH + lane]      = g_XW[w * W1CAT + lane]      + 2.0f * a0;
    g_U[w * HH + 32 + lane] = g_XW[w * W1CAT + 32 + lane] + 2.0f * a1;
}

// h = relu(C0 + L*U + b1)   (C0 at XW cols 128..191)
__global__ void k_spmv_h(const float* __restrict__ b1) {
    int w = (blockIdx.x * blockDim.x + threadIdx.x) >> 5;
    int lane = threadIdx.x & 31;
    if (w >= NN) return;
    int s = g_rowptr[w], e = g_rowptr[w + 1];
    float a0 = 0.f, a1 = 0.f;
    for (int t = s; t < e; t++) {
        int2 cw = g_cw[t];
        float wt = __int_as_float(cw.y);
        const float* p = &g_U[cw.x * HH];
        a0 += wt * p[lane];
        a1 += wt * p[32 + lane];
    }
    float v0 = g_XW[w * W1CAT + 128 + lane] + a0 + b1[lane];
    float v1 = g_XW[w * W1CAT + 160 + lane] + a1 + b1[32 + lane];
    g_h[w * HH + lane]      = fmaxf(v0, 0.0f);
    g_h[w * HH + 32 + lane] = fmaxf(v1, 0.0f);
}

// U2 = A2 + 2*L*B2  (A2 at HW cols 0..39, B2 at cols 40..79; padded stride)
__global__ void k_spmv_U2() {
    int w = (blockIdx.x * blockDim.x + threadIdx.x) >> 5;
    int lane = threadIdx.x & 31;
    if (w >= NN) return;
    int s = g_rowptr[w], e = g_rowptr[w + 1];
    float a0 = 0.f, a1 = 0.f;
    for (int t = s; t < e; t++) {
        int2 cw = g_cw[t];
        float wt = __int_as_float(cw.y);
        const float* p = &g_HW[cw.x * HWPAD + 40];
        a0 += wt * p[lane];
        a1 += wt * p[32 + lane];   // cols 72..103 < 120: in-bounds; only lane<8 used
    }
    g_U2[w * 64 + lane] = g_HW[w * HWPAD + lane] + 2.0f * a0;
    if (lane < 8)
        g_U2[w * 64 + 32 + lane] = g_HW[w * HWPAD + 32 + lane] + 2.0f * a1;
}

// logits = C2 + L*U2 + b2 ; out = log_softmax   (C2 at HW cols 80..119)
__global__ void k_final(const float* __restrict__ b2, float* __restrict__ out) {
    int w = (blockIdx.x * blockDim.x + threadIdx.x) >> 5;
    int lane = threadIdx.x & 31;
    if (w >= NN) return;
    int s = g_rowptr[w], e = g_rowptr[w + 1];
    float a0 = 0.f, a1 = 0.f;
    for (int t = s; t < e; t++) {
        int2 cw = g_cw[t];
        float wt = __int_as_float(cw.y);
        const float* p = &g_U2[cw.x * 64];
        a0 += wt * p[lane];
        if (lane < 8) a1 += wt * p[32 + lane];
    }
    float z0 = g_HW[w * HWPAD + 80 + lane] + a0 + b2[lane];
    float z1 = (lane < 8) ? (g_HW[w * HWPAD + 112 + lane] + a1 + b2[32 + lane])
                          : __int_as_float(0xff800000);
    float m = fmaxf(z0, z1);
    #pragma unroll
    for (int o = 16; o > 0; o >>= 1) m = fmaxf(m, __shfl_xor_sync(0xffffffffu, m, o));
    float ssum = expf(z0 - m) + ((lane < 8) ? expf(z1 - m) : 0.0f);
    #pragma unroll
    for (int o = 16; o > 0; o >>= 1) ssum += __shfl_xor_sync(0xffffffffu, ssum, o);
    float l = logf(ssum);
    out[w * CC + lane] = z0 - m - l;
    if (lane < 8) out[w * CC + 32 + lane] = z1 - m - l;
}

// ---------------- launch -----------------------------------------------------
extern "C" void kernel_launch(void* const* d_in, const int* in_sizes, int n_in,
                              void* d_out, int out_size) {
    // Resolve inputs BY ELEMENT COUNT (all six distinct)
    const float* x  = nullptr;
    const void*  ei = nullptr;
    const float* W1 = nullptr;
    const float* b1 = nullptr;
    const float* W2 = nullptr;
    const float* b2 = nullptr;
    for (int i = 0; i < n_in; i++) {
        switch (in_sizes[i]) {
            case NN * FF:     x  = (const float*)d_in[i]; break;
            case 2 * EE:      ei = d_in[i];               break;
            case 3 * FF * HH: W1 = (const float*)d_in[i]; break;
            case HH:          b1 = (const float*)d_in[i]; break;
            case 3 * HH * CC: W2 = (const float*)d_in[i]; break;
            case CC:          b2 = (const float*)d_in[i]; break;
            default: break;
        }
    }
    const long long* ei64 = (const long long*)ei;
    const int*       ei32 = (const int*)ei;
    float* out = (float*)d_out;

    const int TB = 256;
    int nodeBlocks = (NN + TB - 1) / TB;
    int edgeBlocks = (EE + TB - 1) / TB;
    int warpRowBlocks = (NN * 32 + TB - 1) / TB;
    int gemmBlocks = (NN + 63) / 64;   // 782

    k_detect_dtype<<<1, 1024>>>(ei64);            // #1
    k_init<<<nodeBlocks, TB>>>(W1, W2);           // #2
    k_count_deg<<<edgeBlocks, TB>>>(ei64, ei32);  // #3
    k_gemm1<<<gemmBlocks, 256>>>(x);              // #4 — ncu profiles this slot
    k_scan1<<<SCAN_BLOCKS, 256>>>();              // #5
    k_scan2<<<1, 256>>>();                        // #6
    k_scan3<<<SCAN_BLOCKS, 256>>>();              // #7
    k_fill_csr<<<edgeBlocks, TB>>>(ei64, ei32);   // #8

    k_spmv_U<<<warpRowBlocks, TB>>>();            // #9
    k_spmv_h<<<warpRowBlocks, TB>>>(b1);          // #10
    k_gemm2<<<gemmBlocks, 256>>>();               // #11
    k_spmv_U2<<<warpRowBlocks, TB>>>();           // #12
    k_final<<<warpRowBlocks, TB>>>(b2, out);      // #13
}

// round 16
// speedup vs baseline: 1.1746x; 1.0325x over previous
#include <cuda_runtime.h>

#define NN 50000
#define EE 800000
#define FF 100
#define HH 64
#define CC 40
#define W1CAT 192    // [A=x@W1[1] | B=x@W1[2] | C0=x@(W1[0]-W1[2])]
#define W2CAT 120    // logical [A2 | B2 | C2]
#define HWPAD 128    // padded row stride for g_HW
#define SCAN_BLOCKS ((NN + 255) / 256)   // 196

typedef unsigned long long ull;

// ---------------- scratch (device globals; no allocations allowed) ----------
__device__ int   g_is64;
__device__ int   g_deg[NN];
__device__ int   g_rowptr[NN + 1];
__device__ int   g_cursor[NN];
__device__ int   g_bsum[SCAN_BLOCKS];
__device__ int2  g_cw[EE];           // packed (col, weight-bits)
__device__ float g_dinv[NN];
__device__ float g_Wcat1[FF * W1CAT];
__device__ float g_Wcat2[HH * W2CAT];
__device__ float g_XW[NN * W1CAT];
__device__ float g_U[NN * HH];
__device__ float g_h[NN * HH];
__device__ float g_HW[NN * HWPAD];   // cols 0..119 valid
__device__ float g_U2[NN * 64];      // cols 0..39 valid

// ---------------- f32x2 helpers ----------------------------------------------
#define FMA2(d, a, b, c) \
    asm("fma.rn.f32x2 %0, %1, %2, %3;" : "=l"(d) : "l"(a), "l"(b), "l"(c))

__device__ __forceinline__ ull pack2(float lo, float hi) {
    ull r; asm("mov.b64 %0, {%1, %2};" : "=l"(r) : "f"(lo), "f"(hi)); return r;
}
__device__ __forceinline__ float2 unpack2(ull v) {
    float2 r; asm("mov.b64 {%0, %1}, %2;" : "=f"(r.x), "=f"(r.y) : "l"(v)); return r;
}

// ---------------- dtype detection (parallel) ---------------------------------
__global__ void k_detect_dtype(const long long* __restrict__ ei) {
    __shared__ int s_ok;
    int tid = threadIdx.x;            // 1024 threads
    if (tid == 0) s_ok = 1;
    __syncthreads();
    long long v = ei[tid * 781];      // max index 798,963 < EE
    if (v < 0 || v >= NN) s_ok = 0;
    __syncthreads();
    if (tid == 0) g_is64 = s_ok;
}

// ---------------- init: zero degrees + weight concat (merged) ----------------
__global__ void k_init(const float* __restrict__ W1, const float* __restrict__ W2) {
    int i = blockIdx.x * blockDim.x + threadIdx.x;
    if (i < NN) g_deg[i] = 0;
    if (i < FF * W1CAT) {
        int f = i / W1CAT, j = i % W1CAT;
        float v;
        if (j < 64)       v = W1[6400 + f * 64 + j];
        else if (j < 128) v = W1[12800 + f * 64 + (j - 64)];
        else              v = W1[f * 64 + (j - 128)] - W1[12800 + f * 64 + (j - 128)];
        g_Wcat1[i] = v;
    }
    if (i < HH * W2CAT) {
        int f = i / W2CAT, j = i % W2CAT;
        float v;
        if (j < 40)      v = W2[2560 + f * 40 + j];
        else if (j < 80) v = W2[5120 + f * 40 + (j - 40)];
        else             v = W2[f * 40 + (j - 80)] - W2[5120 + f * 40 + (j - 80)];
        g_Wcat2[i] = v;
    }
}

// ---------------- graph setup ------------------------------------------------
__global__ void k_count_deg(const long long* __restrict__ ei64,
                            const int* __restrict__ ei32) {
    int e = blockIdx.x * blockDim.x + threadIdx.x;
    if (e < EE) {
        long long r = g_is64 ? ei64[e] : (long long)ei32[e];
        if (r >= 0 && r < NN) atomicAdd(&g_deg[(int)r], 1);
    }
}

__global__ void k_scan1() {
    __shared__ int warpsums[8];
    int tid = threadIdx.x;
    int i = blockIdx.x * 256 + tid;
    int d = (i < NN) ? g_deg[i] : 0;

    int lane = tid & 31, wid = tid >> 5;
    int v = d;
    #pragma unroll
    for (int o = 1; o < 32; o <<= 1) {
        int t = __shfl_up_sync(0xffffffffu, v, o);
        if (lane >= o) v += t;
    }
    if (lane == 31) warpsums[wid] = v;
    __syncthreads();
    if (tid == 0) {
        int run = 0;
        #pragma unroll
        for (int k = 0; k < 8; k++) { int t = warpsums[k]; warpsums[k] = run; run += t; }
    }
    __syncthreads();
    int excl = v - d + warpsums[wid];
    if (i < NN) g_rowptr[i] = excl;
    if (tid == 255) g_bsum[blockIdx.x] = excl + d;
}

__global__ void k_scan2() {
    __shared__ int warpsums[8];
    int tid = threadIdx.x;   // 256 threads
    int v0 = (tid < SCAN_BLOCKS) ? g_bsum[tid] : 0;

    int lane = tid & 31, wid = tid >> 5;
    int v = v0;
    #pragma unroll
    for (int o = 1; o < 32; o <<= 1) {
        int t = __shfl_up_sync(0xffffffffu, v, o);
        if (lane >= o) v += t;
    }
    if (lane == 31) warpsums[wid] = v;
    __syncthreads();
    if (tid == 0) {
        int run = 0;
        #pragma unroll
        for (int k = 0; k < 8; k++) { int t = warpsums[k]; warpsums[k] = run; run += t; }
    }
    __syncthreads();
    if (tid < SCAN_BLOCKS) g_bsum[tid] = v - v0 + warpsums[wid];
}

__global__ void k_scan3() {
    int i = blockIdx.x * 256 + threadIdx.x;
    if (i < NN) {
        int r = g_rowptr[i] + g_bsum[blockIdx.x];
        g_rowptr[i] = r;
        g_cursor[i] = r;
        int d = g_deg[i];
        g_dinv[i] = (d > 0) ? rsqrtf((float)d) : 0.0f;
        if (i == NN - 1) g_rowptr[NN] = r + d;
    }
}

__global__ void k_fill_csr(const long long* __restrict__ ei64,
                           const int* __restrict__ ei32) {
    int e = blockIdx.x * blockDim.x + threadIdx.x;
    if (e < EE) {
        long long rl, cl;
        if (g_is64) { rl = ei64[e]; cl = ei64[EE + e]; }
        else        { rl = (long long)ei32[e]; cl = (long long)ei32[EE + e]; }
        if (rl < 0 || rl >= NN || cl < 0 || cl >= NN) return;
        int r = (int)rl, c = (int)cl;
        int pos = atomicAdd(&g_cursor[r], 1);
        if (pos >= 0 && pos < EE) {
            float wt = -(g_dinv[r] * g_dinv[c]);
            g_cw[pos] = make_int2(c, __float_as_int(wt));
        }
    }
}

// ------- f32x2 GEMM, DOUBLE-BUFFERED: BM=64, BN=width, tile 4 x CPT ----------
// One __syncthreads per k-tile: iteration kt reads buf[kt&1] and writes
// buf[(kt+1)&1] (disjoint), so a single end-of-tile barrier is sufficient.
template <int Kd, int BN, int NV, int Ldc>
__device__ __forceinline__ void gemm_f2_core(
    const float* __restrict__ A, const float* __restrict__ B, float* __restrict__ C)
{
    constexpr int CPT = BN / 16;          // 12 or 8 cols per thread
    constexpr int PAIRS = CPT / 2;        // f32x2 accumulators per row
    constexpr int BQ = BN / 4;            // float4s per Bs row
    constexpr int NB4 = (16 * BQ) / 256;  // B float4 loads per thread per ktile
    constexpr int NT = (Kd + 15) / 16;    // k-tiles

    __shared__ __align__(16) ull   As2[2][16][66];   // [buf][k][m] = (a,a)
    __shared__ __align__(16) float Bs[2][16][BN];

    int tid = threadIdx.x;
    int tx = tid & 15, ty = tid >> 4;
    int m0 = blockIdx.x * 64;

    int am = tid >> 2, aq = tid & 3;      // A-staging coords
    int agm = m0 + am;

    ull acc[4][PAIRS];
    #pragma unroll
    for (int i = 0; i < 4; i++)
        #pragma unroll
        for (int j = 0; j < PAIRS; j++) acc[i][j] = 0ull;

    float4 Av;
    float4 Bv[NB4];

    // ---- load tile 0 into registers ----
    auto loadTile = [&](int kt, float4& av, float4* bv) {
        int k0 = kt * 16;
        int gk = k0 + aq * 4;
        av = make_float4(0.f, 0.f, 0.f, 0.f);
        if (agm < NN) {
            if (gk + 4 <= Kd) av = *(const float4*)&A[agm * Kd + gk];
            else {
                float t0 = (gk + 0 < Kd) ? A[agm * Kd + gk + 0] : 0.f;
                float t1 = (gk + 1 < Kd) ? A[agm * Kd + gk + 1] : 0.f;
                float t2 = (gk + 2 < Kd) ? A[agm * Kd + gk + 2] : 0.f;
                float t3 = (gk + 3 < Kd) ? A[agm * Kd + gk + 3] : 0.f;
                av = make_float4(t0, t1, t2, t3);
            }
        }
        #pragma unroll
        for (int c = 0; c < NB4; c++) {
            int idx = c * 256 + tid;
            int row = idx / BQ, c4 = idx % BQ;
            int gkb = k0 + row, gn = c4 * 4;
            float4 v = make_float4(0.f, 0.f, 0.f, 0.f);
            if (gkb < Kd) {
                if (gn + 4 <= NV) v = *(const float4*)&B[gkb * NV + gn];
                else {
                    float t0 = (gn + 0 < NV) ? B[gkb * NV + gn + 0] : 0.f;
                    float t1 = (gn + 1 < NV) ? B[gkb * NV + gn + 1] : 0.f;
                    float t2 = (gn + 2 < NV) ? B[gkb * NV + gn + 2] : 0.f;
                    float t3 = (gn + 3 < NV) ? B[gkb * NV + gn + 3] : 0.f;
                    v = make_float4(t0, t1, t2, t3);
                }
            }
            bv[c] = v;
        }
    };
    auto storeTile = [&](int buf, const float4& av, const float4* bv) {
        As2[buf][aq * 4 + 0][am] = pack2(av.x, av.x);
        As2[buf][aq * 4 + 1][am] = pack2(av.y, av.y);
        As2[buf][aq * 4 + 2][am] = pack2(av.z, av.z);
        As2[buf][aq * 4 + 3][am] = pack2(av.w, av.w);
        #pragma unroll
        for (int c = 0; c < NB4; c++) {
            int idx = c * 256 + tid;
            int row = idx / BQ, c4 = idx % BQ;
            *(float4*)&Bs[buf][row][c4 * 4] = bv[c];
        }
    };

    loadTile(0, Av, Bv);
    storeTile(0, Av, Bv);
    __syncthreads();

    for (int kt = 0; kt < NT; kt++) {
        int cur = kt & 1;
        bool more = (kt + 1 < NT);
        if (more) loadTile(kt + 1, Av, Bv);      // prefetch overlaps compute

        #pragma unroll
        for (int k = 0; k < 16; k++) {
            ulonglong2 aa0 = *(const ulonglong2*)&As2[cur][k][ty * 4];
            ulonglong2 aa1 = *(const ulonglong2*)&As2[cur][k][ty * 4 + 2];
            ull a2[4] = {aa0.x, aa0.y, aa1.x, aa1.y};
            ull b2[PAIRS];
            #pragma unroll
            for (int q = 0; q < PAIRS / 2; q++) {
                ulonglong2 bv = *(const ulonglong2*)&Bs[cur][k][tx * CPT + q * 4];
                b2[q * 2] = bv.x; b2[q * 2 + 1] = bv.y;
            }
            #pragma unroll
            for (int i = 0; i < 4; i++)
                #pragma unroll
                for (int j = 0; j < PAIRS; j++)
                    FMA2(acc[i][j], a2[i], b2[j], acc[i][j]);
        }

        if (more) {
            storeTile(cur ^ 1, Av, Bv);          // disjoint from buf being read
            __syncthreads();
        }
    }

    #pragma unroll
    for (int i = 0; i < 4; i++) {
        int gm = m0 + ty * 4 + i;
        if (gm >= NN) continue;
        #pragma unroll
        for (int q = 0; q < PAIRS / 2; q++) {
            int gn = tx * CPT + q * 4;
            if (gn + 4 <= NV) {
                float2 lo = unpack2(acc[i][q * 2]);
                float2 hi = unpack2(acc[i][q * 2 + 1]);
                *(float4*)&C[gm * Ldc + gn] = make_float4(lo.x, lo.y, hi.x, hi.y);
            }
        }
    }
}

__global__ __launch_bounds__(256, 2) void k_gemm1(const float* __restrict__ x) {
    gemm_f2_core<FF, 192, 192, W1CAT>(x, g_Wcat1, g_XW);
}

__global__ __launch_bounds__(256, 2) void k_gemm2() {
    gemm_f2_core<HH, 128, 120, HWPAD>(g_h, g_Wcat2, g_HW);
}

// ---------------- SpMV kernels (warp-per-row, unroll-2 pipelined) ------------
// U = A + 2*L*B   (A at XW cols 0..63, B at cols 64..127)
__global__ void k_spmv_U() {
    int w = (blockIdx.x * blockDim.x + threadIdx.x) >> 5;
    int lane = threadIdx.x & 31;
    if (w >= NN) return;
    int s = g_rowptr[w], e = g_rowptr[w + 1];
    float a0 = 0.f, a1 = 0.f;
    int t = s;
    for (; t + 1 < e; t += 2) {
        int2 c0 = g_cw[t], c1 = g_cw[t + 1];
        float w0 = __int_as_float(c0.y), w1 = __int_as_float(c1.y);
        const float* p0 = &g_XW[c0.x * W1CAT + 64];
        const float* p1 = &g_XW[c1.x * W1CAT + 64];
        float v00 = p0[lane], v01 = p0[32 + lane];
        float v10 = p1[lane], v11 = p1[32 + lane];
        a0 += w0 * v00 + w1 * v10;
        a1 += w0 * v01 + w1 * v11;
    }
    if (t < e) {
        int2 c0 = g_cw[t];
        float w0 = __int_as_float(c0.y);
        const float* p0 = &g_XW[c0.x * W1CAT + 64];
        a0 += w0 * p0[lane];
        a1 += w0 * p0[32 + lane];
    }
    g_U[w * HH + lane]      = g_XW[w * W1CAT + lane]      + 2.0f * a0;
    g_U[w * HH + 32 + lane] = g_XW[w * W1CAT + 32 + lane] + 2.0f * a1;
}

// h = relu(C0 + L*U + b1)   (C0 at XW cols 128..191)
__global__ void k_spmv_h(const float* __restrict__ b1) {
    int w = (blockIdx.x * blockDim.x + threadIdx.x) >> 5;
    int lane = threadIdx.x & 31;
    if (w >= NN) return;
    int s = g_rowptr[w], e = g_rowptr[w + 1];
    float a0 = 0.f, a1 = 0.f;
    int t = s;
    for (; t + 1 < e; t += 2) {
        int2 c0 = g_cw[t], c1 = g_cw[t + 1];
        float w0 = __int_as_float(c0.y), w1 = __int_as_float(c1.y);
        const float* p0 = &g_U[c0.x * HH];
        const float* p1 = &g_U[c1.x * HH];
        float v00 = p0[lane], v01 = p0[32 + lane];
        float v10 = p1[lane], v11 = p1[32 + lane];
        a0 += w0 * v00 + w1 * v10;
        a1 += w0 * v01 + w1 * v11;
    }
    if (t < e) {
        int2 c0 = g_cw[t];
        float w0 = __int_as_float(c0.y);
        const float* p0 = &g_U[c0.x * HH];
        a0 += w0 * p0[lane];
        a1 += w0 * p0[32 + lane];
    }
    float v0 = g_XW[w * W1CAT + 128 + lane] + a0 + b1[lane];
    float v1 = g_XW[w * W1CAT + 160 + lane] + a1 + b1[32 + lane];
    g_h[w * HH + lane]      = fmaxf(v0, 0.0f);
    g_h[w * HH + 32 + lane] = fmaxf(v1, 0.0f);
}

// U2 = A2 + 2*L*B2  (A2 at HW cols 0..39, B2 at cols 40..79; padded stride)
__global__ void k_spmv_U2() {
    int w = (blockIdx.x * blockDim.x + threadIdx.x) >> 5;
    int lane = threadIdx.x & 31;
    if (w >= NN) return;
    int s = g_rowptr[w], e = g_rowptr[w + 1];
    float a0 = 0.f, a1 = 0.f;
    int t = s;
    for (; t + 1 < e; t += 2) {
        int2 c0 = g_cw[t], c1 = g_cw[t + 1];
        float w0 = __int_as_float(c0.y), w1 = __int_as_float(c1.y);
        const float* p0 = &g_HW[c0.x * HWPAD + 40];
        const float* p1 = &g_HW[c1.x * HWPAD + 40];
        float v00 = p0[lane], v01 = p0[32 + lane];
        float v10 = p1[lane], v11 = p1[32 + lane];
        a0 += w0 * v00 + w1 * v10;
        a1 += w0 * v01 + w1 * v11;     // cols 72..103 < 120: in-bounds; lane<8 used
    }
    if (t < e) {
        int2 c0 = g_cw[t];
        float w0 = __int_as_float(c0.y);
        const float* p0 = &g_HW[c0.x * HWPAD + 40];
        a0 += w0 * p0[lane];
        a1 += w0 * p0[32 + lane];
    }
    g_U2[w * 64 + lane] = g_HW[w * HWPAD + lane] + 2.0f * a0;
    if (lane < 8)
        g_U2[w * 64 + 32 + lane] = g_HW[w * HWPAD + 32 + lane] + 2.0f * a1;
}

// logits = C2 + L*U2 + b2 ; out = log_softmax   (C2 at HW cols 80..119)
__global__ void k_final(const float* __restrict__ b2, float* __restrict__ out) {
    int w = (blockIdx.x * blockDim.x + threadIdx.x) >> 5;
    int lane = threadIdx.x & 31;
    if (w >= NN) return;
    int s = g_rowptr[w], e = g_rowptr[w + 1];
    float a0 = 0.f, a1 = 0.f;
    int t = s;
    for (; t + 1 < e; t += 2) {
        int2 c0 = g_cw[t], c1 = g_cw[t + 1];
        float w0 = __int_as_float(c0.y), w1 = __int_as_float(c1.y);
        const float* p0 = &g_U2[c0.x * 64];
        const float* p1 = &g_U2[c1.x * 64];
        float v00 = p0[lane], v01 = p0[32 + lane];   // col 32..63 in-bounds (padded)
        float v10 = p1[lane], v11 = p1[32 + lane];
        a0 += w0 * v00 + w1 * v10;
        a1 += w0 * v01 + w1 * v11;
    }
    if (t < e) {
        int2 c0 = g_cw[t];
        float w0 = __int_as_float(c0.y);
        const float* p0 = &g_U2[c0.x * 64];
        a0 += w0 * p0[lane];
        a1 += w0 * p0[32 + lane];
    }
    float z0 = g_HW[w * HWPAD + 80 + lane] + a0 + b2[lane];
    float z1 = (lane < 8) ? (g_HW[w * HWPAD + 112 + lane] + a1 + b2[32 + lane])
                          : __int_as_float(0xff800000);
    float m = fmaxf(z0, z1);
    #pragma unroll
    for (int o = 16; o > 0; o >>= 1) m = fmaxf(m, __shfl_xor_sync(0xffffffffu, m, o));
    float ssum = expf(z0 - m) + ((lane < 8) ? expf(z1 - m) : 0.0f);
    #pragma unroll
    for (int o = 16; o > 0; o >>= 1) ssum += __shfl_xor_sync(0xffffffffu, ssum, o);
    float l = logf(ssum);
    out[w * CC + lane] = z0 - m - l;
    if (lane < 8) out[w * CC + 32 + lane] = z1 - m - l;
}

// ---------------- launch -----------------------------------------------------
extern "C" void kernel_launch(void* const* d_in, const int* in_sizes, int n_in,
                              void* d_out, int out_size) {
    // Resolve inputs BY ELEMENT COUNT (all six distinct)
    const float* x  = nullptr;
    const void*  ei = nullptr;
    const float* W1 = nullptr;
    const float* b1 = nullptr;
    const float* W2 = nullptr;
    const float* b2 = nullptr;
    for (int i = 0; i < n_in; i++) {
        switch (in_sizes[i]) {
            case NN * FF:     x  = (const float*)d_in[i]; break;
            case 2 * EE:      ei = d_in[i];               break;
            case 3 * FF * HH: W1 = (const float*)d_in[i]; break;
            case HH:          b1 = (const float*)d_in[i]; break;
            case 3 * HH * CC: W2 = (const float*)d_in[i]; break;
            case CC:          b2 = (const float*)d_in[i]; break;
            default: break;
        }
    }
    const long long* ei64 = (const long long*)ei;
    const int*       ei32 = (const int*)ei;
    float* out = (float*)d_out;

    const int TB = 256;
    int nodeBlocks = (NN + TB - 1) / TB;
    int edgeBlocks = (EE + TB - 1) / TB;
    int warpRowBlocks = (NN * 32 + TB - 1) / TB;
    int gemmBlocks = (NN + 63) / 64;   // 782

    k_detect_dtype<<<1, 1024>>>(ei64);            // #1
    k_init<<<nodeBlocks, TB>>>(W1, W2);           // #2
    k_count_deg<<<edgeBlocks, TB>>>(ei64, ei32);  // #3
    k_gemm1<<<gemmBlocks, 256>>>(x);              // #4 — ncu profiles this slot
    k_scan1<<<SCAN_BLOCKS, 256>>>();              // #5
    k_scan2<<<1, 256>>>();                        // #6
    k_scan3<<<SCAN_BLOCKS, 256>>>();              // #7
    k_fill_csr<<<edgeBlocks, TB>>>(ei64, ei32);   // #8

    k_spmv_U<<<warpRowBlocks, TB>>>();            // #9
    k_spmv_h<<<warpRowBlocks, TB>>>(b1);          // #10
    k_gemm2<<<gemmBlocks, 256>>>();               // #11
    k_spmv_U2<<<warpRowBlocks, TB>>>();           // #12
    k_final<<<warpRowBlocks, TB>>>(b2, out);      // #13
}

// round 17
// speedup vs baseline: 1.2831x; 1.0923x over previous
#include <cuda_runtime.h>

#define NN 50000
#define EE 800000
#define FF 100
#define HH 64
#define CC 40
#define W1CAT 192    // [A=x@W1[1] | B=x@W1[2] | C0=x@(W1[0]-W1[2])]
#define W2CAT 120    // logical [A2 | B2 | C2]
#define HWPAD 128    // padded row stride for g_HW
#define SCAN_BLOCKS ((NN + 255) / 256)   // 196

typedef unsigned long long ull;

// ---------------- scratch (device globals; no allocations allowed) ----------
__device__ int   g_is64;
__device__ int   g_deg[NN];
__device__ int   g_rowptr[NN + 1];
__device__ int   g_cursor[NN];
__device__ int   g_bsum[SCAN_BLOCKS];
__device__ int2  g_cw[EE];           // packed (col, weight-bits)
__device__ float g_dinv[NN];
__device__ float g_Wcat1[FF * W1CAT];
__device__ float g_Wcat2[HH * W2CAT];
__device__ float g_XW[NN * W1CAT];
__device__ float g_U[NN * HH];
__device__ float g_h[NN * HH];
__device__ float g_HW[NN * HWPAD];   // cols 0..119 valid
__device__ float g_U2[NN * 64];      // cols 0..39 valid

// ---------------- f32x2 helpers ----------------------------------------------
#define FMA2(d, a, b, c) \
    asm("fma.rn.f32x2 %0, %1, %2, %3;" : "=l"(d) : "l"(a), "l"(b), "l"(c))

__device__ __forceinline__ ull pack2(float lo, float hi) {
    ull r; asm("mov.b64 %0, {%1, %2};" : "=l"(r) : "f"(lo), "f"(hi)); return r;
}
__device__ __forceinline__ float2 unpack2(ull v) {
    float2 r; asm("mov.b64 {%0, %1}, %2;" : "=f"(r.x), "=f"(r.y) : "l"(v)); return r;
}

// ---------------- dtype detection (parallel) ---------------------------------
__global__ void k_detect_dtype(const long long* __restrict__ ei) {
    __shared__ int s_ok;
    int tid = threadIdx.x;            // 1024 threads
    if (tid == 0) s_ok = 1;
    __syncthreads();
    long long v = ei[tid * 781];      // max index 798,963 < EE
    if (v < 0 || v >= NN) s_ok = 0;
    __syncthreads();
    if (tid == 0) g_is64 = s_ok;
}

// ---------------- init: zero degrees + weight concat (merged) ----------------
__global__ void k_init(const float* __restrict__ W1, const float* __restrict__ W2) {
    int i = blockIdx.x * blockDim.x + threadIdx.x;
    if (i < NN) g_deg[i] = 0;
    if (i < FF * W1CAT) {
        int f = i / W1CAT, j = i % W1CAT;
        float v;
        if (j < 64)       v = W1[6400 + f * 64 + j];
        else if (j < 128) v = W1[12800 + f * 64 + (j - 64)];
        else              v = W1[f * 64 + (j - 128)] - W1[12800 + f * 64 + (j - 128)];
        g_Wcat1[i] = v;
    }
    if (i < HH * W2CAT) {
        int f = i / W2CAT, j = i % W2CAT;
        float v;
        if (j < 40)      v = W2[2560 + f * 40 + j];
        else if (j < 80) v = W2[5120 + f * 40 + (j - 40)];
        else             v = W2[f * 40 + (j - 80)] - W2[5120 + f * 40 + (j - 80)];
        g_Wcat2[i] = v;
    }
}

// ---------------- graph setup ------------------------------------------------
__global__ void k_count_deg(const long long* __restrict__ ei64,
                            const int* __restrict__ ei32) {
    int e = blockIdx.x * blockDim.x + threadIdx.x;
    if (e < EE) {
        long long r = g_is64 ? ei64[e] : (long long)ei32[e];
        if (r >= 0 && r < NN) atomicAdd(&g_deg[(int)r], 1);
    }
}

__global__ void k_scan1() {
    __shared__ int warpsums[8];
    int tid = threadIdx.x;
    int i = blockIdx.x * 256 + tid;
    int d = (i < NN) ? g_deg[i] : 0;

    int lane = tid & 31, wid = tid >> 5;
    int v = d;
    #pragma unroll
    for (int o = 1; o < 32; o <<= 1) {
        int t = __shfl_up_sync(0xffffffffu, v, o);
        if (lane >= o) v += t;
    }
    if (lane == 31) warpsums[wid] = v;
    __syncthreads();
    if (tid == 0) {
        int run = 0;
        #pragma unroll
        for (int k = 0; k < 8; k++) { int t = warpsums[k]; warpsums[k] = run; run += t; }
    }
    __syncthreads();
    int excl = v - d + warpsums[wid];
    if (i < NN) g_rowptr[i] = excl;
    if (tid == 255) g_bsum[blockIdx.x] = excl + d;
}

__global__ void k_scan2() {
    __shared__ int warpsums[8];
    int tid = threadIdx.x;   // 256 threads
    int v0 = (tid < SCAN_BLOCKS) ? g_bsum[tid] : 0;

    int lane = tid & 31, wid = tid >> 5;
    int v = v0;
    #pragma unroll
    for (int o = 1; o < 32; o <<= 1) {
        int t = __shfl_up_sync(0xffffffffu, v, o);
        if (lane >= o) v += t;
    }
    if (lane == 31) warpsums[wid] = v;
    __syncthreads();
    if (tid == 0) {
        int run = 0;
        #pragma unroll
        for (int k = 0; k < 8; k++) { int t = warpsums[k]; warpsums[k] = run; run += t; }
    }
    __syncthreads();
    if (tid < SCAN_BLOCKS) g_bsum[tid] = v - v0 + warpsums[wid];
}

__global__ void k_scan3() {
    int i = blockIdx.x * 256 + threadIdx.x;
    if (i < NN) {
        int r = g_rowptr[i] + g_bsum[blockIdx.x];
        g_rowptr[i] = r;
        g_cursor[i] = r;
        int d = g_deg[i];
        g_dinv[i] = (d > 0) ? rsqrtf((float)d) : 0.0f;
        if (i == NN - 1) g_rowptr[NN] = r + d;
    }
}

__global__ void k_fill_csr(const long long* __restrict__ ei64,
                           const int* __restrict__ ei32) {
    int e = blockIdx.x * blockDim.x + threadIdx.x;
    if (e < EE) {
        long long rl, cl;
        if (g_is64) { rl = ei64[e]; cl = ei64[EE + e]; }
        else        { rl = (long long)ei32[e]; cl = (long long)ei32[EE + e]; }
        if (rl < 0 || rl >= NN || cl < 0 || cl >= NN) return;
        int r = (int)rl, c = (int)cl;
        int pos = atomicAdd(&g_cursor[r], 1);
        if (pos >= 0 && pos < EE) {
            float wt = -(g_dinv[r] * g_dinv[c]);
            g_cw[pos] = make_int2(c, __float_as_int(wt));
        }
    }
}

// -------- f32x2 GEMM, 8-row tiles: BM=128, BN=width, thread tile 8 x CPT -----
// A staged in shared as PLAIN floats (un-duplicated): 0.83 B of LDS per MAC.
// (a,a) pairs are formed in registers via mov.b64 (alu pipe, cheap).
// Double-buffered with one __syncthreads per k-tile (disjoint read/write bufs).
template <int Kd, int BN, int NV, int Ldc>
__device__ __forceinline__ void gemm_f2_core(
    const float* __restrict__ A, const float* __restrict__ B, float* __restrict__ C)
{
    constexpr int CPT = BN / 16;          // 12 or 8 cols per thread
    constexpr int PAIRS = CPT / 2;        // f32x2 accumulators per row
    constexpr int BQ = BN / 4;            // float4s per Bs row
    constexpr int NB4 = (16 * BQ) / 256;  // B float4 loads per thread per ktile
    constexpr int NT = (Kd + 15) / 16;    // k-tiles

    __shared__ __align__(16) float As[2][16][132];   // [buf][k][m], m<128
    __shared__ __align__(16) float Bs[2][16][BN];

    int tid = threadIdx.x;
    int tx = tid & 15, ty = tid >> 4;     // thread rows: ty*8..ty*8+7
    int m0 = blockIdx.x * 128;

    int am = tid >> 1, aq = tid & 1;      // A staging: row am, k-half aq (8 k)
    int agm = m0 + am;

    ull acc[8][PAIRS];
    #pragma unroll
    for (int i = 0; i < 8; i++)
        #pragma unroll
        for (int j = 0; j < PAIRS; j++) acc[i][j] = 0ull;

    float4 Av[2];
    float4 Bv[NB4];

    auto loadTile = [&](int kt) {
        int k0 = kt * 16;
        #pragma unroll
        for (int h = 0; h < 2; h++) {
            int gk = k0 + aq * 8 + h * 4;
            float4 v = make_float4(0.f, 0.f, 0.f, 0.f);
            if (agm < NN) {
                if (gk + 4 <= Kd) v = *(const float4*)&A[agm * Kd + gk];
                else {
                    float t0 = (gk + 0 < Kd) ? A[agm * Kd + gk + 0] : 0.f;
                    float t1 = (gk + 1 < Kd) ? A[agm * Kd + gk + 1] : 0.f;
                    float t2 = (gk + 2 < Kd) ? A[agm * Kd + gk + 2] : 0.f;
                    float t3 = (gk + 3 < Kd) ? A[agm * Kd + gk + 3] : 0.f;
                    v = make_float4(t0, t1, t2, t3);
                }
            }
            Av[h] = v;
        }
        #pragma unroll
        for (int c = 0; c < NB4; c++) {
            int idx = c * 256 + tid;
            int row = idx / BQ, c4 = idx % BQ;
            int gkb = k0 + row, gn = c4 * 4;
            float4 v = make_float4(0.f, 0.f, 0.f, 0.f);
            if (gkb < Kd) {
                if (gn + 4 <= NV) v = *(const float4*)&B[gkb * NV + gn];
                else {
                    float t0 = (gn + 0 < NV) ? B[gkb * NV + gn + 0] : 0.f;
                    float t1 = (gn + 1 < NV) ? B[gkb * NV + gn + 1] : 0.f;
                    float t2 = (gn + 2 < NV) ? B[gkb * NV + gn + 2] : 0.f;
                    float t3 = (gn + 3 < NV) ? B[gkb * NV + gn + 3] : 0.f;
                    v = make_float4(t0, t1, t2, t3);
                }
            }
            Bv[c] = v;
        }
    };
    auto storeTile = [&](int buf) {
        int kb = aq * 8;
        As[buf][kb + 0][am] = Av[0].x;
        As[buf][kb + 1][am] = Av[0].y;
        As[buf][kb + 2][am] = Av[0].z;
        As[buf][kb + 3][am] = Av[0].w;
        As[buf][kb + 4][am] = Av[1].x;
        As[buf][kb + 5][am] = Av[1].y;
        As[buf][kb + 6][am] = Av[1].z;
        As[buf][kb + 7][am] = Av[1].w;
        #pragma unroll
        for (int c = 0; c < NB4; c++) {
            int idx = c * 256 + tid;
            int row = idx / BQ, c4 = idx % BQ;
            *(float4*)&Bs[buf][row][c4 * 4] = Bv[c];
        }
    };

    loadTile(0);
    storeTile(0);
    __syncthreads();

    for (int kt = 0; kt < NT; kt++) {
        int cur = kt & 1;
        bool more = (kt + 1 < NT);
        if (more) loadTile(kt + 1);              // prefetch overlaps compute

        #pragma unroll
        for (int k = 0; k < 16; k++) {
            float4 af0 = *(const float4*)&As[cur][k][ty * 8];
            float4 af1 = *(const float4*)&As[cur][k][ty * 8 + 4];
            ull a2[8];
            a2[0] = pack2(af0.x, af0.x); a2[1] = pack2(af0.y, af0.y);
            a2[2] = pack2(af0.z, af0.z); a2[3] = pack2(af0.w, af0.w);
            a2[4] = pack2(af1.x, af1.x); a2[5] = pack2(af1.y, af1.y);
            a2[6] = pack2(af1.z, af1.z); a2[7] = pack2(af1.w, af1.w);
            ull b2[PAIRS];
            #pragma unroll
            for (int q = 0; q < PAIRS / 2; q++) {
                ulonglong2 bv = *(const ulonglong2*)&Bs[cur][k][tx * CPT + q * 4];
                b2[q * 2] = bv.x; b2[q * 2 + 1] = bv.y;
            }
            #pragma unroll
            for (int i = 0; i < 8; i++)
                #pragma unroll
                for (int j = 0; j < PAIRS; j++)
                    FMA2(acc[i][j], a2[i], b2[j], acc[i][j]);
        }

        if (more) {
            storeTile(cur ^ 1);                  // disjoint from buf being read
            __syncthreads();
        }
    }

    #pragma unroll
    for (int i = 0; i < 8; i++) {
        int gm = m0 + ty * 8 + i;
        if (gm >= NN) continue;
        #pragma unroll
        for (int q = 0; q < PAIRS / 2; q++) {
            int gn = tx * CPT + q * 4;
            if (gn + 4 <= NV) {
                float2 lo = unpack2(acc[i][q * 2]);
                float2 hi = unpack2(acc[i][q * 2 + 1]);
                *(float4*)&C[gm * Ldc + gn] = make_float4(lo.x, lo.y, hi.x, hi.y);
            }
        }
    }
}

__global__ __launch_bounds__(256, 1) void k_gemm1(const float* __restrict__ x) {
    gemm_f2_core<FF, 192, 192, W1CAT>(x, g_Wcat1, g_XW);
}

__global__ __launch_bounds__(256, 1) void k_gemm2() {
    gemm_f2_core<HH, 128, 120, HWPAD>(g_h, g_Wcat2, g_HW);
}

// ---------------- SpMV kernels (warp-per-row, unroll-2 pipelined) ------------
// U = A + 2*L*B   (A at XW cols 0..63, B at cols 64..127)
__global__ void k_spmv_U() {
    int w = (blockIdx.x * blockDim.x + threadIdx.x) >> 5;
    int lane = threadIdx.x & 31;
    if (w >= NN) return;
    int s = g_rowptr[w], e = g_rowptr[w + 1];
    float a0 = 0.f, a1 = 0.f;
    int t = s;
    for (; t + 1 < e; t += 2) {
        int2 c0 = g_cw[t], c1 = g_cw[t + 1];
        float w0 = __int_as_float(c0.y), w1 = __int_as_float(c1.y);
        const float* p0 = &g_XW[c0.x * W1CAT + 64];
        const float* p1 = &g_XW[c1.x * W1CAT + 64];
        float v00 = p0[lane], v01 = p0[32 + lane];
        float v10 = p1[lane], v11 = p1[32 + lane];
        a0 += w0 * v00 + w1 * v10;
        a1 += w0 * v01 + w1 * v11;
    }
    if (t < e) {
        int2 c0 = g_cw[t];
        float w0 = __int_as_float(c0.y);
        const float* p0 = &g_XW[c0.x * W1CAT + 64];
        a0 += w0 * p0[lane];
        a1 += w0 * p0[32 + lane];
    }
    g_U[w * HH + lane]      = g_XW[w * W1CAT + lane]      + 2.0f * a0;
    g_U[w * HH + 32 + lane] = g_XW[w * W1CAT + 32 + lane] + 2.0f * a1;
}

// h = relu(C0 + L*U + b1)   (C0 at XW cols 128..191)
__global__ void k_spmv_h(const float* __restrict__ b1) {
    int w = (blockIdx.x * blockDim.x + threadIdx.x) >> 5;
    int lane = threadIdx.x & 31;
    if (w >= NN) return;
    int s = g_rowptr[w], e = g_rowptr[w + 1];
    float a0 = 0.f, a1 = 0.f;
    int t = s;
    for (; t + 1 < e; t += 2) {
        int2 c0 = g_cw[t], c1 = g_cw[t + 1];
        float w0 = __int_as_float(c0.y), w1 = __int_as_float(c1.y);
        const float* p0 = &g_U[c0.x * HH];
        const float* p1 = &g_U[c1.x * HH];
        float v00 = p0[lane], v01 = p0[32 + lane];
        float v10 = p1[lane], v11 = p1[32 + lane];
        a0 += w0 * v00 + w1 * v10;
        a1 += w0 * v01 + w1 * v11;
    }
    if (t < e) {
        int2 c0 = g_cw[t];
        float w0 = __int_as_float(c0.y);
        const float* p0 = &g_U[c0.x * HH];
        a0 += w0 * p0[lane];
        a1 += w0 * p0[32 + lane];
    }
    float v0 = g_XW[w * W1CAT + 128 + lane] + a0 + b1[lane];
    float v1 = g_XW[w * W1CAT + 160 + lane] + a1 + b1[32 + lane];
    g_h[w * HH + lane]      = fmaxf(v0, 0.0f);
    g_h[w * HH + 32 + lane] = fmaxf(v1, 0.0f);
}

// U2 = A2 + 2*L*B2  (A2 at HW cols 0..39, B2 at cols 40..79; padded stride)
__global__ void k_spmv_U2() {
    int w = (blockIdx.x * blockDim.x + threadIdx.x) >> 5;
    int lane = threadIdx.x & 31;
    if (w >= NN) return;
    int s = g_rowptr[w], e = g_rowptr[w + 1];
    float a0 = 0.f, a1 = 0.f;
    int t = s;
    for (; t + 1 < e; t += 2) {
        int2 c0 = g_cw[t], c1 = g_cw[t + 1];
        float w0 = __int_as_float(c0.y), w1 = __int_as_float(c1.y);
        const float* p0 = &g_HW[c0.x * HWPAD + 40];
        const float* p1 = &g_HW[c1.x * HWPAD + 40];
        float v00 = p0[lane], v01 = p0[32 + lane];
        float v10 = p1[lane], v11 = p1[32 + lane];
        a0 += w0 * v00 + w1 * v10;
        a1 += w0 * v01 + w1 * v11;     // cols 72..103 < 120: in-bounds; lane<8 used
    }
    if (t < e) {
        int2 c0 = g_cw[t];
        float w0 = __int_as_float(c0.y);
        const float* p0 = &g_HW[c0.x * HWPAD + 40];
        a0 += w0 * p0[lane];
        a1 += w0 * p0[32 + lane];
    }
    g_U2[w * 64 + lane] = g_HW[w * HWPAD + lane] + 2.0f * a0;
    if (lane < 8)
        g_U2[w * 64 + 32 + lane] = g_HW[w * HWPAD + 32 + lane] + 2.0f * a1;
}

// logits = C2 + L*U2 + b2 ; out = log_softmax   (C2 at HW cols 80..119)
__global__ void k_final(const float* __restrict__ b2, float* __restrict__ out) {
    int w = (blockIdx.x * blockDim.x + threadIdx.x) >> 5;
    int lane = threadIdx.x & 31;
    if (w >= NN) return;
    int s = g_rowptr[w], e = g_rowptr[w + 1];
    float a0 = 0.f, a1 = 0.f;
    int t = s;
    for (; t + 1 < e; t += 2) {
        int2 c0 = g_cw[t], c1 = g_cw[t + 1];
        float w0 = __int_as_float(c0.y), w1 = __int_as_float(c1.y);
        const float* p0 = &g_U2[c0.x * 64];
        const float* p1 = &g_U2[c1.x * 64];
        float v00 = p0[lane], v01 = p0[32 + lane];   // col 32..63 in-bounds (padded)
        float v10 = p1[lane], v11 = p1[32 + lane];
        a0 += w0 * v00 + w1 * v10;
        a1 += w0 * v01 + w1 * v11;
    }
    if (t < e) {
        int2 c0 = g_cw[t];
        float w0 = __int_as_float(c0.y);
        const float* p0 = &g_U2[c0.x * 64];
        a0 += w0 * p0[lane];
        a1 += w0 * p0[32 + lane];
    }
    float z0 = g_HW[w * HWPAD + 80 + lane] + a0 + b2[lane];
    float z1 = (lane < 8) ? (g_HW[w * HWPAD + 112 + lane] + a1 + b2[32 + lane])
                          : __int_as_float(0xff800000);
    float m = fmaxf(z0, z1);
    #pragma unroll
    for (int o = 16; o > 0; o >>= 1) m = fmaxf(m, __shfl_xor_sync(0xffffffffu, m, o));
    float ssum = expf(z0 - m) + ((lane < 8) ? expf(z1 - m) : 0.0f);
    #pragma unroll
    for (int o = 16; o > 0; o >>= 1) ssum += __shfl_xor_sync(0xffffffffu, ssum, o);
    float l = logf(ssum);
    out[w * CC + lane] = z0 - m - l;
    if (lane < 8) out[w * CC + 32 + lane] = z1 - m - l;
}

// ---------------- launch -----------------------------------------------------
extern "C" void kernel_launch(void* const* d_in, const int* in_sizes, int n_in,
                              void* d_out, int out_size) {
    // Resolve inputs BY ELEMENT COUNT (all six distinct)
    const float* x  = nullptr;
    const void*  ei = nullptr;
    const float* W1 = nullptr;
    const float* b1 = nullptr;
    const float* W2 = nullptr;
    const float* b2 = nullptr;
    for (int i = 0; i < n_in; i++) {
        switch (in_sizes[i]) {
            case NN * FF:     x  = (const float*)d_in[i]; break;
            case 2 * EE:      ei = d_in[i];               break;
            case 3 * FF * HH: W1 = (const float*)d_in[i]; break;
            case HH:          b1 = (const float*)d_in[i]; break;
            case 3 * HH * CC: W2 = (const float*)d_in[i]; break;
            case CC:          b2 = (const float*)d_in[i]; break;
            default: break;
        }
    }
    const long long* ei64 = (const long long*)ei;
    const int*       ei32 = (const int*)ei;
    float* out = (float*)d_out;

    const int TB = 256;
    int nodeBlocks = (NN + TB - 1) / TB;
    int edgeBlocks = (EE + TB - 1) / TB;
    int warpRowBlocks = (NN * 32 + TB - 1) / TB;
    int gemmBlocks = (NN + 127) / 128;   // 391

    k_detect_dtype<<<1, 1024>>>(ei64);            // #1
    k_init<<<nodeBlocks, TB>>>(W1, W2);           // #2
    k_count_deg<<<edgeBlocks, TB>>>(ei64, ei32);  // #3
    k_gemm1<<<gemmBlocks, 256>>>(x);              // #4 — ncu profiles this slot
    k_scan1<<<SCAN_BLOCKS, 256>>>();              // #5
    k_scan2<<<1, 256>>>();                        // #6
    k_scan3<<<SCAN_BLOCKS, 256>>>();              // #7
    k_fill_csr<<<edgeBlocks, TB>>>(ei64, ei32);   // #8

    k_spmv_U<<<warpRowBlocks, TB>>>();            // #9
    k_spmv_h<<<warpRowBlocks, TB>>>(b1);          // #10
    k_gemm2<<<gemmBlocks, 256>>>();               // #11
    k_spmv_U2<<<warpRowBlocks, TB>>>();           // #12
    k_final<<<warpRowBlocks, TB>>>(b2, out);      // #13
}